// round 4
// baseline (speedup 1.0000x reference)
#include <cuda_runtime.h>

#define BLK  64     // batches per CTA == threads per CTA
#define STR  65     // padded shared row stride (bank-conflict-free)
#define NN   64     // number of unknowns (N)
#define NP   65     // N + 1
#define LAM3  1e-4f // V_LAMBDA / DT^6 (DT = 1)
#define RIDGE 1e-4f

// DTD band coefficients (times LAM3), a = column index in [1, 64]:
__device__ __forceinline__ constexpr float C0f(int a) {
    return (a == 1) ? 10.f : (a == 2) ? 19.f :
           (a <= 61) ? 20.f : (a == 62) ? 19.f : (a == 63) ? 10.f : 1.f;
}
__device__ __forceinline__ constexpr float C1f(int a) {
    return (a == 1) ? -12.f : (a <= 61) ? -15.f :
           (a == 62) ? -12.f : (a == 63) ? -3.f : 0.f;
}
__device__ __forceinline__ constexpr float C2f(int a) {
    return (a <= 61) ? 6.f : (a == 62) ? 3.f : 0.f;
}
__device__ __forceinline__ constexpr float C3f(int a) {
    return (a <= 61) ? -1.f : 0.f;
}

// Shared layout (floats, rows of stride STR):
//  sth : NP rows   theta staging
//  sgx : NN rows   2*dxy.x
//  sgy : NN rows   2*dxy.y
//  se  : NN rows   e_j = cos(th_j)cos(th_j+1)+sin..sin  (j=0..63)
//  srh : NN rows   fully assembled rhs_j
//  sm1/sm2/sm3 : NN rows  L[j+m][j] * inv_j
//  szs : NN rows   z_j * inv_j
//  sou : NP rows   output staging
#define SMEM_FLOATS ((2*NP + 8*NN) * STR)

__global__ __launch_bounds__(BLK, 1) void AlpamayoR1_solve_kernel(
    const float* __restrict__ dxy,
    const float* __restrict__ theta,
    const float* __restrict__ v0,
    float* __restrict__ out, int B)
{
    extern __shared__ float sm[];
    float* sth = sm;
    float* sgx = sth + NP*STR;
    float* sgy = sgx + NN*STR;
    float* se  = sgy + NN*STR;
    float* srh = se  + NN*STR;
    float* sm1 = srh + NN*STR;
    float* sm2 = sm1 + NN*STR;
    float* sm3 = sm2 + NN*STR;
    float* szs = sm3 + NN*STR;
    float* sou = szs + NN*STR;

    const int t  = threadIdx.x;
    const int b0 = blockIdx.x * BLK;

    // ---- coalesced load + transpose into padded shared ----
    for (int idx = t; idx < BLK * NP; idx += BLK) {
        int bl = idx / NP;
        int k  = idx - bl * NP;
        sth[k * STR + bl] = theta[(size_t)b0 * NP + idx];
    }
    const float2* dxy2 = (const float2*)dxy;
    for (int idx = t; idx < BLK * NN; idx += BLK) {
        float2 v = dxy2[(size_t)b0 * NN + idx];
        int bl = idx / NN;
        int i  = idx - bl * NN;
        sgx[i * STR + bl] = 2.0f * v.x;
        sgy[i * STR + bl] = 2.0f * v.y;
    }
    float v0v = v0[b0 + t];
    __syncthreads();

    // ---- Pass AB (parallel over k): sincos + e_j + rhs_j assembly ----
    // carry c,s,gx,gy of index k-1 in registers; never store sin/cos.
    {
        float thp = sth[t];
        float sp, cp; __sincosf(thp, &sp, &cp);
        float gxp = sgx[t];
        float gyp = sgy[t];
        float e0v = 0.f;
        #pragma unroll
        for (int k = 1; k <= NN; ++k) {
            float th = sth[k * STR + t];
            float s, c; __sincosf(th, &s, &c);
            float gx = 0.f, gy = 0.f;
            if (k < NN) { gx = sgx[k * STR + t]; gy = sgy[k * STR + t]; }
            float e  = cp * c + sp * s;            // e_{k-1}
            float rh = c * (gxp + gx) + s * (gyp + gy);
            if (k == 1) { e0v = e; rh -= (e0v - 3.f * LAM3) * v0v; }
            if (k == 2) rh -= 3.f * LAM3 * v0v;
            if (k == 3) rh += LAM3 * v0v;
            se [(k - 1) * STR + t] = e;
            srh[(k - 1) * STR + t] = rh;
            cp = c; sp = s; gxp = gx; gyp = gy;
        }
    }

    // ---- Pass C (serial): band Cholesky + forward solve, registers only ----
    {
        float L1p  = 0.f;
        float L2p1 = 0.f, L2p2 = 0.f;
        float L3p1 = 0.f, L3p2 = 0.f, L3p3 = 0.f;
        float zp1  = 0.f, zp2  = 0.f, zp3  = 0.f;

        float e_next = se[1 * STR + t];   // e_{j+1} for j=0
        float rh_cur = srh[t];            // rhs_0

        #pragma unroll
        for (int j = 0; j < NN; ++j) {
            // prefetch next iteration's operands (off the critical chain)
            float e_n2 = (j + 2 <= NN - 1) ? se[(j + 2) * STR + t] : 0.f;
            float rh_n = (j + 1 <= NN - 1) ? srh[(j + 1) * STR + t] : 0.f;

            float a0 = ((j < NN - 1) ? 2.f : 1.f) + LAM3 * C0f(j + 1) + RIDGE;
            float d  = a0 - L1p * L1p - L2p2 * L2p2 - L3p3 * L3p3;
            float inv = rsqrtf(d);

            float s1v = (j < NN - 1)
                      ? (e_next + LAM3 * C1f(j + 1) - L2p1 * L1p - L3p2 * L2p2) : 0.f;
            float s2v = (j < NN - 2) ? (LAM3 * C2f(j + 1) - L3p1 * L1p) : 0.f;
            float s3v = (j < NN - 3) ? (LAM3 * C3f(j + 1)) : 0.f;

            float L1 = s1v * inv;
            float L2 = s2v * inv;
            float L3 = s3v * inv;
            float z  = (rh_cur - L1p * zp1 - L2p2 * zp2 - L3p3 * zp3) * inv;

            sm1[j * STR + t] = L1 * inv;
            sm2[j * STR + t] = L2 * inv;
            sm3[j * STR + t] = L3 * inv;
            szs[j * STR + t] = z  * inv;

            L3p3 = L3p2; L3p2 = L3p1; L3p1 = L3;
            L2p2 = L2p1; L2p1 = L2;
            L1p  = L1;
            zp3  = zp2;  zp2  = zp1;  zp1  = z;
            e_next = e_n2; rh_cur = rh_n;
        }
    }

    // ---- Pass D: back substitution (1-FMA-deep chain) ----
    {
        float y1 = 0.f, y2 = 0.f, y3 = 0.f;
        #pragma unroll
        for (int j = NN - 1; j >= 0; --j) {
            // tmp depends only on y2,y3 (available one iteration earlier)
            float tmp = szs[j * STR + t]
                      - sm2[j * STR + t] * y2
                      - sm3[j * STR + t] * y3;
            float y = tmp - sm1[j * STR + t] * y1;
            sou[(j + 1) * STR + t] = y;
            y3 = y2; y2 = y1; y1 = y;
        }
        sou[t] = v0v;
    }
    __syncthreads();

    // ---- coalesced store ----
    for (int idx = t; idx < BLK * NP; idx += BLK) {
        int bl = idx / NP;
        int k  = idx - bl * NP;
        out[(size_t)b0 * NP + idx] = sou[k * STR + bl];
    }
}

extern "C" void kernel_launch(void* const* d_in, const int* in_sizes, int n_in,
                              void* d_out, int out_size) {
    const float* dxy   = (const float*)d_in[0];
    const float* theta = (const float*)d_in[1];
    const float* v0    = (const float*)d_in[2];
    float* out = (float*)d_out;
    int B = in_sizes[2];

    size_t smem = (size_t)SMEM_FLOATS * sizeof(float);
    cudaFuncSetAttribute(AlpamayoR1_solve_kernel,
                         cudaFuncAttributeMaxDynamicSharedMemorySize, (int)smem);
    int grid = (B + BLK - 1) / BLK;
    AlpamayoR1_solve_kernel<<<grid, BLK, smem>>>(dxy, theta, v0, out, B);
}

// round 5
// speedup vs baseline: 1.2247x; 1.2247x over previous
#include <cuda_runtime.h>

#define BLK  64     // batches per CTA == threads per CTA
#define STR  65     // padded shared row stride (bank-conflict-free)
#define NN   64     // number of unknowns (N)
#define NP   65     // N + 1
#define LAM3  1e-4f // V_LAMBDA / DT^6 (DT = 1)
#define RIDGE 1e-4f

// DTD band coefficients, a = column index in [1, 64]:
__host__ __device__ __forceinline__ float C0f(int a) {
    return (a == 1) ? 10.f : (a == 2) ? 19.f :
           (a <= 61) ? 20.f : (a == 62) ? 19.f : (a == 63) ? 10.f : 1.f;
}
__host__ __device__ __forceinline__ float C1f(int a) {
    return (a == 1) ? -12.f : (a <= 61) ? -15.f :
           (a == 62) ? -12.f : (a == 63) ? -3.f : 0.f;
}
__host__ __device__ __forceinline__ float C2f(int a) {
    return (a <= 61) ? 6.f : (a == 62) ? 3.f : 0.f;
}
__host__ __device__ __forceinline__ float C3f(int a) {
    return (a <= 61) ? -1.f : 0.f;
}

// Shared layout:
//  s4   : NN*BLK float4   packed (L1*inv, L2*inv, L3*inv, z*inv)
//  sth  : 67 rows * STR   theta staging (+2 zero pad rows)
//  sgx  : 66 rows * STR   2*dxy.x (+2 zero pad rows)
//  sgy  : 66 rows * STR   2*dxy.y (+2 zero pad rows)
//  sou  : NP rows * STR   output staging
//  sCb4 : NN float4       per-column band constants (broadcast reads)
#define S4_F4    (NN*BLK)
#define STH_F    (67*STR)
#define SGX_F    (66*STR)
#define SOU_F    (NP*STR)
#define SMEM_BYTES (S4_F4*16 + (STH_F + 2*SGX_F + SOU_F)*4 + NN*16)

__global__ __launch_bounds__(BLK, 1) void AlpamayoR1_solve_kernel(
    const float* __restrict__ dxy,
    const float* __restrict__ theta,
    const float* __restrict__ v0,
    float* __restrict__ out, int B)
{
    extern __shared__ float4 smem4[];
    float4* s4   = smem4;
    float*  sth  = (float*)(s4 + S4_F4);
    float*  sgx  = sth + STH_F;
    float*  sgy  = sgx + SGX_F;
    float*  sou  = sgy + SGX_F;
    float4* sCb4 = (float4*)(sou + SOU_F);

    const int t  = threadIdx.x;
    const int b0 = blockIdx.x * BLK;

    // ---- per-column band constant table (computed once, broadcast later) ----
    {
        int a = t + 1;                       // column index 1..64
        float base = (t < NN - 1) ? 2.f : 1.f;
        sCb4[t] = make_float4(base + LAM3 * C0f(a) + RIDGE,
                              LAM3 * C1f(a),
                              LAM3 * C2f(a),
                              LAM3 * C3f(a));
    }

    // ---- zero pad rows ----
    sth[65 * STR + t] = 0.f;
    sth[66 * STR + t] = 0.f;
    sgx[64 * STR + t] = 0.f;
    sgx[65 * STR + t] = 0.f;
    sgy[64 * STR + t] = 0.f;
    sgy[65 * STR + t] = 0.f;

    // ---- theta staging: float4 coalesced loads, scattered scalar STS ----
    {
        const float4* th4 = (const float4*)(theta + (size_t)b0 * NP); // 16B aligned
        for (int i = t; i < (BLK * NP) / 4; i += BLK) {   // 1040 float4
            float4 v = th4[i];
            int f = 4 * i;
            int bl0 = f / NP, k0 = f - bl0 * NP;
            sth[k0 * STR + bl0] = v.x;
            int f1 = f + 1; int bl1 = f1 / NP, k1 = f1 - bl1 * NP;
            sth[k1 * STR + bl1] = v.y;
            int f2 = f + 2; int bl2 = f2 / NP, k2 = f2 - bl2 * NP;
            sth[k2 * STR + bl2] = v.z;
            int f3 = f + 3; int bl3 = f3 / NP, k3 = f3 - bl3 * NP;
            sth[k3 * STR + bl3] = v.w;
        }
    }
    // ---- dxy staging: each float4 = (x,y) of steps (2u, 2u+1) of one batch ----
    {
        const float4* dx4 = (const float4*)(dxy + (size_t)b0 * NN * 2);
        #pragma unroll 4
        for (int i = t; i < (BLK * NN) / 2; i += BLK) {   // 2048 float4
            float4 v = dx4[i];
            int bl = i >> 5;            // 32 float4 per batch
            int s0 = (i & 31) * 2;
            sgx[s0 * STR + bl]       = 2.f * v.x;
            sgy[s0 * STR + bl]       = 2.f * v.y;
            sgx[(s0 + 1) * STR + bl] = 2.f * v.z;
            sgy[(s0 + 1) * STR + bl] = 2.f * v.w;
        }
    }
    float v0v = v0[b0 + t];
    __syncthreads();

    // ---- prologue ----
    float th0 = sth[t];       float s0v, c0v; __sincosf(th0, &s0v, &c0v);
    float th1 = sth[STR + t]; float sA, cA;   __sincosf(th1, &sA, &cA);
    const float e0 = c0v * cA + s0v * sA;
    float gxj = sgx[t],       gyj = sgy[t];
    float thn = sth[2 * STR + t];         // theta[j+2] for j=0
    float gxn = sgx[STR + t];             // gx[j+1]
    float gyn = sgy[STR + t];

    // rolling Cholesky state
    float L1p  = 0.f;
    float L2p1 = 0.f, L2p2 = 0.f;
    float L3p1 = 0.f, L3p2 = 0.f, L3p3 = 0.f;
    float zp1  = 0.f, zp2  = 0.f, zp3  = 0.f;

    #pragma unroll 8
    for (int j = 0; j < NN; ++j) {
        // sincos of this iter's lookahead theta (loaded last iter)
        float sB, cB; __sincosf(thn, &sB, &cB);

        // prefetch next iteration's operands (pad rows make these safe)
        float thn2 = sth[(j + 3) * STR + t];
        float gxn2 = sgx[(j + 2) * STR + t];
        float gyn2 = sgy[(j + 2) * STR + t];
        float4 cb  = sCb4[j];            // broadcast, conflict-free

        float e1  = cA * cB + sA * sB;
        if (j == NN - 1) e1 = 0.f;       // pad theta leaks cos(0)=1 otherwise
        float rhs = cA * (gxj + gxn) + sA * (gyj + gyn);
        if (j == 0) rhs -= (e0 - 3.f * LAM3) * v0v;
        if (j == 1) rhs -= 3.f * LAM3 * v0v;
        if (j == 2) rhs += LAM3 * v0v;

        // pivot (critical chain: registers only)
        float d   = cb.x - L1p * L1p - L2p2 * L2p2 - L3p3 * L3p3;
        float inv = rsqrtf(d);

        float s1v = e1 + cb.y - L2p1 * L1p - L3p2 * L2p2;
        float s2v = cb.z - L3p1 * L1p;   // auto-zero at edges (L3 already 0)
        float s3v = cb.w;

        float L1 = s1v * inv;
        float L2 = s2v * inv;
        float L3 = s3v * inv;
        float z  = (rhs - L1p * zp1 - L2p2 * zp2 - L3p3 * zp3) * inv;

        float4 pk;
        pk.x = L1 * inv; pk.y = L2 * inv; pk.z = L3 * inv; pk.w = z * inv;
        s4[j * BLK + t] = pk;            // one STS.128

        L3p3 = L3p2; L3p2 = L3p1; L3p1 = L3;
        L2p2 = L2p1; L2p1 = L2;
        L1p  = L1;
        zp3  = zp2;  zp2  = zp1;  zp1  = z;
        cA = cB; sA = sB;
        gxj = gxn; gyj = gyn;
        thn = thn2; gxn = gxn2; gyn = gyn2;
    }

    // ---- back substitution: one LDS.128 per step, 1-FMA-deep y chain ----
    {
        float y1 = 0.f, y2 = 0.f, y3 = 0.f;
        #pragma unroll 8
        for (int j = NN - 1; j >= 0; --j) {
            float4 pk = s4[j * BLK + t];
            float tmp = pk.w - pk.y * y2 - pk.z * y3;   // independent of y1
            float y   = tmp - pk.x * y1;
            sou[(j + 1) * STR + t] = y;
            y3 = y2; y2 = y1; y1 = y;
        }
        sou[t] = v0v;
    }
    __syncthreads();

    // ---- coalesced float4 store (gather scalars from sou) ----
    {
        float4* out4 = (float4*)(out + (size_t)b0 * NP);
        for (int i = t; i < (BLK * NP) / 4; i += BLK) {
            int f = 4 * i;
            int bl0 = f / NP, k0 = f - bl0 * NP;
            int f1 = f + 1; int bl1 = f1 / NP, k1 = f1 - bl1 * NP;
            int f2 = f + 2; int bl2 = f2 / NP, k2 = f2 - bl2 * NP;
            int f3 = f + 3; int bl3 = f3 / NP, k3 = f3 - bl3 * NP;
            float4 v;
            v.x = sou[k0 * STR + bl0];
            v.y = sou[k1 * STR + bl1];
            v.z = sou[k2 * STR + bl2];
            v.w = sou[k3 * STR + bl3];
            out4[i] = v;
        }
    }
}

extern "C" void kernel_launch(void* const* d_in, const int* in_sizes, int n_in,
                              void* d_out, int out_size) {
    const float* dxy   = (const float*)d_in[0];
    const float* theta = (const float*)d_in[1];
    const float* v0    = (const float*)d_in[2];
    float* out = (float*)d_out;
    int B = in_sizes[2];

    cudaFuncSetAttribute(AlpamayoR1_solve_kernel,
                         cudaFuncAttributeMaxDynamicSharedMemorySize, SMEM_BYTES);
    int grid = (B + BLK - 1) / BLK;
    AlpamayoR1_solve_kernel<<<grid, BLK, SMEM_BYTES>>>(dxy, theta, v0, out, B);
}